// round 11
// baseline (speedup 1.0000x reference)
#include <cuda_runtime.h>

#define BATCH 32
#define DIM 96
#define HH 128
#define WW 128
#define CR 24            // DIM / 4
#define KK 9             // 3x3
#define PLANE_ELEMS (HH * WW)          // 16384
#define PLANE_F4 (PLANE_ELEMS / 4)     // 4096
#define NPLANES (BATCH * DIM)          // 3072
#define BN_EPS 1e-5f

#define GROUPS 8
#define SPG (BATCH / GROUPS)           // 4 samples per group
#define PPG (SPG * DIM)                // 384 planes per group (25 MB)
#define LAG 2                          // window = LAG groups

// scratch (no allocations allowed)
__device__ float g_pooled[NPLANES];          // [b][c] mean
__device__ float g_wdyn[NPLANES * KK];       // [b][c][3][3]

// ---------------------------------------------------------------------------
// Kernel 1: global average pool per plane (within group). Warms L2 for conv.
// ---------------------------------------------------------------------------
__global__ void pool_kernel(const float* __restrict__ x, int base_plane) {
    const int plane = base_plane + blockIdx.x;
    const float4* __restrict__ x4 = (const float4*)(x) + (size_t)plane * PLANE_F4;
    const int tid = threadIdx.x;

    float acc = 0.f;
#pragma unroll 4
    for (int i = tid; i < PLANE_F4; i += 256) {
        float4 v = x4[i];
        acc += (v.x + v.y) + (v.z + v.w);
    }
#pragma unroll
    for (int off = 16; off > 0; off >>= 1)
        acc += __shfl_xor_sync(0xffffffffu, acc, off);

    __shared__ float warp_sums[8];
    if ((tid & 31) == 0) warp_sums[tid >> 5] = acc;
    __syncthreads();
    if (tid == 0) {
        float s = 0.f;
#pragma unroll
        for (int w = 0; w < 8; w++) s += warp_sums[w];
        g_pooled[plane] = s * (1.0f / (float)PLANE_ELEMS);
    }
}

// ---------------------------------------------------------------------------
// Kernel 2: dynamic weight generation. One block per sample in group.
// ---------------------------------------------------------------------------
__global__ void weight_kernel(const float* __restrict__ w1,      // [CR, DIM]
                              const float* __restrict__ gamma,
                              const float* __restrict__ beta,
                              const float* __restrict__ rmean,
                              const float* __restrict__ rvar,
                              const float* __restrict__ w2,      // [DIM*KK, CR]
                              const float* __restrict__ b2,
                              int base_sample) {
    const int b = base_sample + blockIdx.x;
    const int tid = threadIdx.x;   // 128 threads

    __shared__ float pooled_s[DIM];
    __shared__ float h1_s[CR];

    if (tid < DIM) pooled_s[tid] = g_pooled[b * DIM + tid];
    __syncthreads();

    if (tid < CR) {
        float acc = 0.f;
        const float* wrow = w1 + tid * DIM;
#pragma unroll 8
        for (int i = 0; i < DIM; i++) acc += pooled_s[i] * wrow[i];
        float z = (acc - rmean[tid]) * rsqrtf(rvar[tid] + BN_EPS) * gamma[tid] + beta[tid];
        h1_s[tid] = 1.0f / (1.0f + __expf(-z));
    }
    __syncthreads();

    const int nout = DIM * KK;  // 864
    for (int o = tid; o < nout; o += 128) {
        const float* wrow = w2 + o * CR;
        float acc = b2[o];
#pragma unroll
        for (int i = 0; i < CR; i++) acc += h1_s[i] * wrow[i];
        g_wdyn[b * nout + o] = acc;
    }
}

// ---------------------------------------------------------------------------
// Kernel 3: depthwise 3x3 for one group. Register sliding window + prefetch,
// SHFL column halo (lane 0/31 = true zero pad). Reads should hit the
// pool-warmed L2 window; output stores are streaming (__stcs).
// ---------------------------------------------------------------------------
#define CHUNKS 4
#define CHUNK_H (HH / CHUNKS)   // 32

__global__ __launch_bounds__(128) void dwconv_kernel(const float* __restrict__ x,
                                                     const float* __restrict__ bias,
                                                     float* __restrict__ out,
                                                     int base_plane) {
    const int wid = threadIdx.x >> 5;
    const int tx  = threadIdx.x & 31;
    const int lin = blockIdx.x * 4 + wid;
    const int plane = base_plane + (lin >> 2);
    const int chunk = lin & 3;
    const int c = plane % DIM;
    const int r0 = chunk * CHUNK_H;

    const float4* __restrict__ x4   = (const float4*)(x) + (size_t)plane * PLANE_F4;
    float4*       __restrict__ out4 = (float4*)(out)     + (size_t)plane * PLANE_F4;

    const float* wp = g_wdyn + plane * KK;
    const float w00 = wp[0], w01 = wp[1], w02 = wp[2];
    const float w10 = wp[3], w11 = wp[4], w12 = wp[5];
    const float w20 = wp[6], w21 = wp[7], w22 = wp[8];
    const float bv = bias[c];

    const float4 zero4 = make_float4(0.f, 0.f, 0.f, 0.f);

    float4 vA = (r0 == 0) ? zero4 : x4[(r0 - 1) * 32 + tx];
    float4 vB = x4[r0 * 32 + tx];
    float4 vC = (r0 + 1 < HH) ? x4[(r0 + 1) * 32 + tx] : zero4;
    float4 pre = (r0 + 2 < HH) ? x4[(r0 + 2) * 32 + tx] : zero4;

    float lA = __shfl_up_sync(0xffffffffu, vA.w, 1);
    float rA = __shfl_down_sync(0xffffffffu, vA.x, 1);
    float lB = __shfl_up_sync(0xffffffffu, vB.w, 1);
    float rB = __shfl_down_sync(0xffffffffu, vB.x, 1);
    if (tx == 0)  { lA = 0.f; lB = 0.f; }
    if (tx == 31) { rA = 0.f; rB = 0.f; }

#pragma unroll 8
    for (int i = 0; i < CHUNK_H; i++) {
        float lC = __shfl_up_sync(0xffffffffu, vC.w, 1);
        float rC = __shfl_down_sync(0xffffffffu, vC.x, 1);
        if (tx == 0)  lC = 0.f;
        if (tx == 31) rC = 0.f;

        float4 o;
        o.x = bv + w00 * lA   + w01 * vA.x + w02 * vA.y
                 + w10 * lB   + w11 * vB.x + w12 * vB.y
                 + w20 * lC   + w21 * vC.x + w22 * vC.y;
        o.y = bv + w00 * vA.x + w01 * vA.y + w02 * vA.z
                 + w10 * vB.x + w11 * vB.y + w12 * vB.z
                 + w20 * vC.x + w21 * vC.y + w22 * vC.z;
        o.z = bv + w00 * vA.y + w01 * vA.z + w02 * vA.w
                 + w10 * vB.y + w11 * vB.z + w12 * vB.w
                 + w20 * vC.y + w21 * vC.z + w22 * vC.w;
        o.w = bv + w00 * vA.z + w01 * vA.w + w02 * rA
                 + w10 * vB.z + w11 * vB.w + w12 * rB
                 + w20 * vC.z + w21 * vC.w + w22 * rC;

        __stcs(&out4[(r0 + i) * 32 + tx], o);

        vA = vB; lA = lB; rA = rB;
        vB = vC; lB = lC; rB = rC;
        vC = pre;
        const int rp = r0 + i + 3;
        pre = (rp < HH) ? x4[rp * 32 + tx] : zero4;
    }
}

// ---------------------------------------------------------------------------
// Pipelined launch: pool chain on the capture (default) stream, weight+conv
// chain on a secondary stream, linked by events; backpressure keeps the
// in-flight x window to LAG groups so conv reads hit L2.
// ---------------------------------------------------------------------------
extern "C" void kernel_launch(void* const* d_in, const int* in_sizes, int n_in,
                              void* d_out, int out_size) {
    const float* x     = (const float*)d_in[0];
    const float* w1    = (const float*)d_in[1];
    const float* gamma = (const float*)d_in[2];
    const float* beta  = (const float*)d_in[3];
    const float* rmean = (const float*)d_in[4];
    const float* rvar  = (const float*)d_in[5];
    const float* w2    = (const float*)d_in[6];
    const float* b2    = (const float*)d_in[7];
    const float* bias  = (const float*)d_in[8];
    float* out = (float*)d_out;

    // one-time resource creation (happens on the live correctness call,
    // before graph capture; nothing allocated on the device)
    static cudaStream_t s_conv = 0;
    static cudaEvent_t evP[GROUPS], evC[GROUPS];
    static int inited = 0;
    if (!inited) {
        cudaStreamCreateWithFlags(&s_conv, cudaStreamNonBlocking);
        for (int g = 0; g < GROUPS; g++) {
            cudaEventCreateWithFlags(&evP[g], cudaEventDisableTiming);
            cudaEventCreateWithFlags(&evC[g], cudaEventDisableTiming);
        }
        inited = 1;
    }

    for (int g = 0; g < GROUPS; g++) {
        const int base_sample = g * SPG;
        const int base_plane  = base_sample * DIM;

        // backpressure: don't stream group g's x until conv of group g-LAG done
        if (g >= LAG) cudaStreamWaitEvent(0, evC[g - LAG], 0);

        pool_kernel<<<PPG, 256, 0, 0>>>(x, base_plane);
        cudaEventRecord(evP[g], 0);

        cudaStreamWaitEvent(s_conv, evP[g], 0);
        weight_kernel<<<SPG, 128, 0, s_conv>>>(w1, gamma, beta, rmean, rvar,
                                               w2, b2, base_sample);
        dwconv_kernel<<<PPG, 128, 0, s_conv>>>(x, bias, out, base_plane);
        cudaEventRecord(evC[g], s_conv);
    }

    // join the side stream back into the captured origin stream
    cudaStreamWaitEvent(0, evC[GROUPS - 1], 0);
}

// round 13
// speedup vs baseline: 1.8264x; 1.8264x over previous
#include <cuda_runtime.h>

#define BATCH 32
#define DIM 96
#define HH 128
#define WW 128
#define CR 24            // DIM / 4
#define KK 9             // 3x3
#define PLANE_ELEMS (HH * WW)          // 16384
#define PLANE_F4 (PLANE_ELEMS / 4)     // 4096
#define NPLANES (BATCH * DIM)          // 3072
#define BN_EPS 1e-5f

// scratch (no allocations allowed); zero-initialized at module load
__device__ float g_pooled[NPLANES];          // [b][c] mean
__device__ float g_wdyn[NPLANES * KK];       // [b][c][3][3]
__device__ int   g_scnt[BATCH];              // per-sample pool completion count

// ---------------------------------------------------------------------------
// Kernel 1: global average pool per (b,c) plane + fused weight generation.
// One block per plane. The LAST block to finish within a sample (atomic
// counter) also computes that sample's dynamic weights with its 256 threads,
// then resets the counter to 0 (clean state for graph replays).
// ---------------------------------------------------------------------------
__global__ void pool_kernel(const float* __restrict__ x,
                            const float* __restrict__ w1,      // [CR, DIM]
                            const float* __restrict__ gamma,
                            const float* __restrict__ beta,
                            const float* __restrict__ rmean,
                            const float* __restrict__ rvar,
                            const float* __restrict__ w2,      // [DIM*KK, CR]
                            const float* __restrict__ b2) {
    const int plane  = blockIdx.x;
    const int sample = plane / DIM;
    const float4* __restrict__ x4 = (const float4*)(x) + (size_t)plane * PLANE_F4;
    const int tid = threadIdx.x;

    float acc = 0.f;
#pragma unroll 4
    for (int i = tid; i < PLANE_F4; i += 256) {
        float4 v = x4[i];
        acc += (v.x + v.y) + (v.z + v.w);
    }
#pragma unroll
    for (int off = 16; off > 0; off >>= 1)
        acc += __shfl_xor_sync(0xffffffffu, acc, off);

    __shared__ float warp_sums[8];
    __shared__ int s_last;
    if ((tid & 31) == 0) warp_sums[tid >> 5] = acc;
    __syncthreads();
    if (tid == 0) {
        float s = 0.f;
#pragma unroll
        for (int w = 0; w < 8; w++) s += warp_sums[w];
        g_pooled[plane] = s * (1.0f / (float)PLANE_ELEMS);
        __threadfence();
        s_last = (atomicAdd(&g_scnt[sample], 1) == DIM - 1);
    }
    __syncthreads();
    if (!s_last) return;

    // ---- last block of this sample: weight generation ----
    __shared__ float pooled_s[DIM];
    __shared__ float h1_s[CR];

    if (tid == 0) g_scnt[sample] = 0;       // self-reset for graph replay
    if (tid < DIM) pooled_s[tid] = g_pooled[sample * DIM + tid];
    __syncthreads();

    if (tid < CR) {
        const float* wrow = w1 + tid * DIM;
        float a = 0.f;
#pragma unroll 8
        for (int i = 0; i < DIM; i++) a += pooled_s[i] * wrow[i];
        float z = (a - rmean[tid]) * rsqrtf(rvar[tid] + BN_EPS) * gamma[tid] + beta[tid];
        h1_s[tid] = 1.0f / (1.0f + __expf(-z));
    }
    __syncthreads();

    const int nout = DIM * KK;  // 864
    for (int o = tid; o < nout; o += 256) {
        const float* wrow = w2 + o * CR;
        float a = b2[o];
#pragma unroll
        for (int i = 0; i < CR; i++) a += h1_s[i] * wrow[i];
        g_wdyn[sample * nout + o] = a;
    }
}

// ---------------------------------------------------------------------------
// Kernel 2: per-sample depthwise 3x3, stride 1, pad 1 — register window, no
// smem. One WARP per (plane, 32-row chunk); lane tx owns cols [4tx,4tx+4).
// Prefetch 2 rows ahead + unroll 8. Column halo via SHFL; lane 0/31 edges are
// the true zero pad. Reversed plane order reuses pool's L2 tail.
// ---------------------------------------------------------------------------
#define CHUNKS 4
#define CHUNK_H (HH / CHUNKS)   // 32

__global__ __launch_bounds__(128) void dwconv_kernel(const float* __restrict__ x,
                                                     const float* __restrict__ bias,
                                                     float* __restrict__ out) {
    const int wid = threadIdx.x >> 5;
    const int tx  = threadIdx.x & 31;
    const int lin = blockIdx.x * 4 + wid;          // 0 .. NPLANES*CHUNKS-1
    const int plane = (NPLANES - 1) - (lin >> 2);  // reversed plane order
    const int chunk = lin & 3;
    const int c = plane % DIM;
    const int r0 = chunk * CHUNK_H;

    const float4* __restrict__ x4   = (const float4*)(x) + (size_t)plane * PLANE_F4;
    float4*       __restrict__ out4 = (float4*)(out)     + (size_t)plane * PLANE_F4;

    const float* wp = g_wdyn + plane * KK;         // uniform -> broadcast loads
    const float w00 = wp[0], w01 = wp[1], w02 = wp[2];
    const float w10 = wp[3], w11 = wp[4], w12 = wp[5];
    const float w20 = wp[6], w21 = wp[7], w22 = wp[8];
    const float bv = bias[c];

    const float4 zero4 = make_float4(0.f, 0.f, 0.f, 0.f);

    // window rows: A = r-1, B = r, C = r+1 ; pre = r+2 (prefetch)
    float4 vA = (r0 == 0) ? zero4 : x4[(r0 - 1) * 32 + tx];
    float4 vB = x4[r0 * 32 + tx];
    float4 vC = (r0 + 1 < HH) ? x4[(r0 + 1) * 32 + tx] : zero4;
    float4 pre = (r0 + 2 < HH) ? x4[(r0 + 2) * 32 + tx] : zero4;

    float lA = __shfl_up_sync(0xffffffffu, vA.w, 1);
    float rA = __shfl_down_sync(0xffffffffu, vA.x, 1);
    float lB = __shfl_up_sync(0xffffffffu, vB.w, 1);
    float rB = __shfl_down_sync(0xffffffffu, vB.x, 1);
    if (tx == 0)  { lA = 0.f; lB = 0.f; }
    if (tx == 31) { rA = 0.f; rB = 0.f; }

#pragma unroll 8
    for (int i = 0; i < CHUNK_H; i++) {
        float lC = __shfl_up_sync(0xffffffffu, vC.w, 1);
        float rC = __shfl_down_sync(0xffffffffu, vC.x, 1);
        if (tx == 0)  lC = 0.f;
        if (tx == 31) rC = 0.f;

        float4 o;
        o.x = bv + w00 * lA   + w01 * vA.x + w02 * vA.y
                 + w10 * lB   + w11 * vB.x + w12 * vB.y
                 + w20 * lC   + w21 * vC.x + w22 * vC.y;
        o.y = bv + w00 * vA.x + w01 * vA.y + w02 * vA.z
                 + w10 * vB.x + w11 * vB.y + w12 * vB.z
                 + w20 * vC.x + w21 * vC.y + w22 * vC.z;
        o.z = bv + w00 * vA.y + w01 * vA.z + w02 * vA.w
                 + w10 * vB.y + w11 * vB.z + w12 * vB.w
                 + w20 * vC.y + w21 * vC.z + w22 * vC.w;
        o.w = bv + w00 * vA.z + w01 * vA.w + w02 * rA
                 + w10 * vB.z + w11 * vB.w + w12 * rB
                 + w20 * vC.z + w21 * vC.w + w22 * rC;

        out4[(r0 + i) * 32 + tx] = o;

        vA = vB; lA = lB; rA = rB;
        vB = vC; lB = lC; rB = rC;
        vC = pre;
        const int rp = r0 + i + 3;
        pre = (rp < HH) ? x4[rp * 32 + tx] : zero4;
    }
}

// ---------------------------------------------------------------------------
extern "C" void kernel_launch(void* const* d_in, const int* in_sizes, int n_in,
                              void* d_out, int out_size) {
    const float* x     = (const float*)d_in[0];
    const float* w1    = (const float*)d_in[1];
    const float* gamma = (const float*)d_in[2];
    const float* beta  = (const float*)d_in[3];
    const float* rmean = (const float*)d_in[4];
    const float* rvar  = (const float*)d_in[5];
    const float* w2    = (const float*)d_in[6];
    const float* b2    = (const float*)d_in[7];
    const float* bias  = (const float*)d_in[8];
    float* out = (float*)d_out;

    pool_kernel<<<NPLANES, 256>>>(x, w1, gamma, beta, rmean, rvar, w2, b2);
    dwconv_kernel<<<NPLANES, 128>>>(x, bias, out);
}

// round 14
// speedup vs baseline: 1.8436x; 1.0094x over previous
#include <cuda_runtime.h>

#define BATCH 32
#define DIM 96
#define HH 128
#define WW 128
#define CR 24            // DIM / 4
#define KK 9             // 3x3
#define PLANE_ELEMS (HH * WW)          // 16384
#define PLANE_F4 (PLANE_ELEMS / 4)     // 4096
#define NPLANES (BATCH * DIM)          // 3072
#define BN_EPS 1e-5f

// scratch (no allocations allowed); zero-initialized at module load
__device__ float g_pooled[NPLANES];          // [b][c] mean
__device__ float g_wdyn[NPLANES * KK];       // [b][c][3][3]
__device__ int   g_scnt[BATCH];              // per-sample pool completion count

// ---------------------------------------------------------------------------
// Kernel 1: global average pool per (b,c) plane + fused weight generation.
// One block per plane. The LAST block to finish within a sample (atomic
// counter) also computes that sample's dynamic weights with its 256 threads,
// then resets the counter to 0 (clean state for graph replays).
// (Measured-good in R13; unchanged.)
// ---------------------------------------------------------------------------
__global__ void pool_kernel(const float* __restrict__ x,
                            const float* __restrict__ w1,      // [CR, DIM]
                            const float* __restrict__ gamma,
                            const float* __restrict__ beta,
                            const float* __restrict__ rmean,
                            const float* __restrict__ rvar,
                            const float* __restrict__ w2,      // [DIM*KK, CR]
                            const float* __restrict__ b2) {
    const int plane  = blockIdx.x;
    const int sample = plane / DIM;
    const float4* __restrict__ x4 = (const float4*)(x) + (size_t)plane * PLANE_F4;
    const int tid = threadIdx.x;

    float acc = 0.f;
#pragma unroll 4
    for (int i = tid; i < PLANE_F4; i += 256) {
        float4 v = x4[i];
        acc += (v.x + v.y) + (v.z + v.w);
    }
#pragma unroll
    for (int off = 16; off > 0; off >>= 1)
        acc += __shfl_xor_sync(0xffffffffu, acc, off);

    __shared__ float warp_sums[8];
    __shared__ int s_last;
    if ((tid & 31) == 0) warp_sums[tid >> 5] = acc;
    __syncthreads();
    if (tid == 0) {
        float s = 0.f;
#pragma unroll
        for (int w = 0; w < 8; w++) s += warp_sums[w];
        g_pooled[plane] = s * (1.0f / (float)PLANE_ELEMS);
        __threadfence();
        s_last = (atomicAdd(&g_scnt[sample], 1) == DIM - 1);
    }
    __syncthreads();
    if (!s_last) return;

    // ---- last block of this sample: weight generation ----
    __shared__ float pooled_s[DIM];
    __shared__ float h1_s[CR];

    if (tid == 0) g_scnt[sample] = 0;       // self-reset for graph replay
    if (tid < DIM) pooled_s[tid] = g_pooled[sample * DIM + tid];
    __syncthreads();

    if (tid < CR) {
        const float* wrow = w1 + tid * DIM;
        float a = 0.f;
#pragma unroll 8
        for (int i = 0; i < DIM; i++) a += pooled_s[i] * wrow[i];
        float z = (a - rmean[tid]) * rsqrtf(rvar[tid] + BN_EPS) * gamma[tid] + beta[tid];
        h1_s[tid] = 1.0f / (1.0f + __expf(-z));
    }
    __syncthreads();

    const int nout = DIM * KK;  // 864
    for (int o = tid; o < nout; o += 256) {
        const float* wrow = w2 + o * CR;
        float a = b2[o];
#pragma unroll
        for (int i = 0; i < CR; i++) a += h1_s[i] * wrow[i];
        g_wdyn[sample * nout + o] = a;
    }
}

// ---------------------------------------------------------------------------
// Kernel 2: per-sample depthwise 3x3, stride 1, pad 1 — register window, no
// smem, no prefetch (prefetch cost 64 regs -> 8 blocks/SM; this version
// targets ~42 regs -> 12 blocks/SM). One WARP per (plane, 32-row chunk);
// lane tx owns cols [4tx,4tx+4). Column halo via SHFL; lane 0/31 edges are
// the true zero pad. Reversed plane order reuses pool's L2 tail.
// ---------------------------------------------------------------------------
#define CHUNKS 4
#define CHUNK_H (HH / CHUNKS)   // 32

__global__ __launch_bounds__(128, 12) void dwconv_kernel(const float* __restrict__ x,
                                                         const float* __restrict__ bias,
                                                         float* __restrict__ out) {
    const int wid = threadIdx.x >> 5;
    const int tx  = threadIdx.x & 31;
    const int lin = blockIdx.x * 4 + wid;          // 0 .. NPLANES*CHUNKS-1
    const int plane = (NPLANES - 1) - (lin >> 2);  // reversed plane order
    const int chunk = lin & 3;
    const int c = plane % DIM;
    const int r0 = chunk * CHUNK_H;

    const float4* __restrict__ x4   = (const float4*)(x) + (size_t)plane * PLANE_F4;
    float4*       __restrict__ out4 = (float4*)(out)     + (size_t)plane * PLANE_F4;

    const float* wp = g_wdyn + plane * KK;         // uniform -> broadcast loads
    const float w00 = wp[0], w01 = wp[1], w02 = wp[2];
    const float w10 = wp[3], w11 = wp[4], w12 = wp[5];
    const float w20 = wp[6], w21 = wp[7], w22 = wp[8];
    const float bv = bias[c];

    const float4 zero4 = make_float4(0.f, 0.f, 0.f, 0.f);

    // window rows: A = r-1, B = r, C = r+1
    float4 vA = (r0 == 0) ? zero4 : x4[(r0 - 1) * 32 + tx];
    float4 vB = x4[r0 * 32 + tx];
    float lA = __shfl_up_sync(0xffffffffu, vA.w, 1);
    float rA = __shfl_down_sync(0xffffffffu, vA.x, 1);
    float lB = __shfl_up_sync(0xffffffffu, vB.w, 1);
    float rB = __shfl_down_sync(0xffffffffu, vB.x, 1);
    if (tx == 0)  { lA = 0.f; lB = 0.f; }
    if (tx == 31) { rA = 0.f; rB = 0.f; }

#pragma unroll 8
    for (int i = 0; i < CHUNK_H; i++) {
        const int rn = r0 + i + 1;
        float4 vC = (rn < HH) ? x4[rn * 32 + tx] : zero4;
        float lC = __shfl_up_sync(0xffffffffu, vC.w, 1);
        float rC = __shfl_down_sync(0xffffffffu, vC.x, 1);
        if (tx == 0)  lC = 0.f;
        if (tx == 31) rC = 0.f;

        float4 o;
        o.x = bv + w00 * lA   + w01 * vA.x + w02 * vA.y
                 + w10 * lB   + w11 * vB.x + w12 * vB.y
                 + w20 * lC   + w21 * vC.x + w22 * vC.y;
        o.y = bv + w00 * vA.x + w01 * vA.y + w02 * vA.z
                 + w10 * vB.x + w11 * vB.y + w12 * vB.z
                 + w20 * vC.x + w21 * vC.y + w22 * vC.z;
        o.z = bv + w00 * vA.y + w01 * vA.z + w02 * vA.w
                 + w10 * vB.y + w11 * vB.z + w12 * vB.w
                 + w20 * vC.y + w21 * vC.z + w22 * vC.w;
        o.w = bv + w00 * vA.z + w01 * vA.w + w02 * rA
                 + w10 * vB.z + w11 * vB.w + w12 * rB
                 + w20 * vC.z + w21 * vC.w + w22 * rC;

        out4[(r0 + i) * 32 + tx] = o;

        vA = vB; lA = lB; rA = rB;
        vB = vC; lB = lC; rB = rC;
    }
}

// ---------------------------------------------------------------------------
extern "C" void kernel_launch(void* const* d_in, const int* in_sizes, int n_in,
                              void* d_out, int out_size) {
    const float* x     = (const float*)d_in[0];
    const float* w1    = (const float*)d_in[1];
    const float* gamma = (const float*)d_in[2];
    const float* beta  = (const float*)d_in[3];
    const float* rmean = (const float*)d_in[4];
    const float* rvar  = (const float*)d_in[5];
    const float* w2    = (const float*)d_in[6];
    const float* b2    = (const float*)d_in[7];
    const float* bias  = (const float*)d_in[8];
    float* out = (float*)d_out;

    pool_kernel<<<NPLANES, 256>>>(x, w1, gamma, beta, rmean, rvar, w2, b2);
    dwconv_kernel<<<NPLANES, 128>>>(x, bias, out);
}